// round 1
// baseline (speedup 1.0000x reference)
#include <cuda_runtime.h>
#include <cstdint>

// Round 1: correct fp32 SIMT baseline.
// C[M,N] = ternarize(S[N,K]) applied to X[M,K] along K, then threshold at 1.0.
// 128x128x16 tiling, 256 threads, 8x8 register micro-tile per thread.

#define BM 128
#define BN 128
#define BK 16
#define TM 8
#define TN 8

__device__ __forceinline__ float ternarize(float s) {
    // (-1 / 0 / +1) at threshold 1.0
    return (s > 1.0f) ? 1.0f : ((s < -1.0f) ? -1.0f : 0.0f);
}

__global__ __launch_bounds__(256, 2)
void snn_gemm_kernel(const float* __restrict__ X,   // [M, K] row-major
                     const float* __restrict__ S,   // [N, K] row-major
                     float* __restrict__ Out,       // [M, N] row-major
                     int M, int N, int K) {
    __shared__ float Xs[BK][BM + 4];
    __shared__ float Ws[BK][BN + 4];

    const int bm = blockIdx.y;
    const int bn = blockIdx.x;
    const int tid = (int)threadIdx.x;       // 0..255
    const int tx = tid & 15;                // 0..15
    const int ty = tid >> 4;                // 0..15

    const float* Xg = X + (size_t)bm * BM * K;
    const float* Sg = S + (size_t)bn * BN * K;

    float acc[TM][TN];
#pragma unroll
    for (int i = 0; i < TM; i++)
#pragma unroll
        for (int j = 0; j < TN; j++)
            acc[i][j] = 0.0f;

    for (int k0 = 0; k0 < K; k0 += BK) {
        // ---- load tiles (each tile: 128 rows x 16 cols = 512 float4) ----
#pragma unroll
        for (int i = 0; i < 2; i++) {
            int id = tid + i * 256;          // 0..511
            int r  = id >> 2;                // 0..127
            int c4 = (id & 3) * 4;           // 0,4,8,12

            float4 vx = *reinterpret_cast<const float4*>(Xg + (size_t)r * K + k0 + c4);
            Xs[c4 + 0][r] = vx.x;
            Xs[c4 + 1][r] = vx.y;
            Xs[c4 + 2][r] = vx.z;
            Xs[c4 + 3][r] = vx.w;

            float4 vs = *reinterpret_cast<const float4*>(Sg + (size_t)r * K + k0 + c4);
            Ws[c4 + 0][r] = ternarize(vs.x);
            Ws[c4 + 1][r] = ternarize(vs.y);
            Ws[c4 + 2][r] = ternarize(vs.z);
            Ws[c4 + 3][r] = ternarize(vs.w);
        }
        __syncthreads();

        // ---- compute ----
#pragma unroll
        for (int k = 0; k < BK; k++) {
            float a[TM], b[TN];
#pragma unroll
            for (int i = 0; i < TM; i += 4) {
                float4 v = *reinterpret_cast<const float4*>(&Xs[k][ty * TM + i]);
                a[i + 0] = v.x; a[i + 1] = v.y; a[i + 2] = v.z; a[i + 3] = v.w;
            }
#pragma unroll
            for (int j = 0; j < TN; j += 4) {
                float4 v = *reinterpret_cast<const float4*>(&Ws[k][tx * TN + j]);
                b[j + 0] = v.x; b[j + 1] = v.y; b[j + 2] = v.z; b[j + 3] = v.w;
            }
#pragma unroll
            for (int i = 0; i < TM; i++)
#pragma unroll
                for (int j = 0; j < TN; j++)
                    acc[i][j] += a[i] * b[j];
        }
        __syncthreads();
    }

    // ---- epilogue: spike threshold, vectorized stores ----
    const int row0 = bm * BM + ty * TM;
    const int col0 = bn * BN + tx * TN;
#pragma unroll
    for (int i = 0; i < TM; i++) {
        float4 o0, o1;
        o0.x = (acc[i][0] >= 1.0f) ? 1.0f : 0.0f;
        o0.y = (acc[i][1] >= 1.0f) ? 1.0f : 0.0f;
        o0.z = (acc[i][2] >= 1.0f) ? 1.0f : 0.0f;
        o0.w = (acc[i][3] >= 1.0f) ? 1.0f : 0.0f;
        o1.x = (acc[i][4] >= 1.0f) ? 1.0f : 0.0f;
        o1.y = (acc[i][5] >= 1.0f) ? 1.0f : 0.0f;
        o1.z = (acc[i][6] >= 1.0f) ? 1.0f : 0.0f;
        o1.w = (acc[i][7] >= 1.0f) ? 1.0f : 0.0f;
        float* p = Out + (size_t)(row0 + i) * N + col0;
        *reinterpret_cast<float4*>(p)     = o0;
        *reinterpret_cast<float4*>(p + 4) = o1;
    }
}

extern "C" void kernel_launch(void* const* d_in, const int* in_sizes, int n_in,
                              void* d_out, int out_size) {
    const float* X = (const float*)d_in[0];   // spike_input  [M, K]
    const float* S = (const float*)d_in[1];   // synapse_states [N, K]
    float* Out = (float*)d_out;

    const int K = 4096;
    const int M = in_sizes[0] / K;            // 8192
    const int N = in_sizes[1] / K;            // 4096

    dim3 grid(N / BN, M / BM);                // (32, 64)
    snn_gemm_kernel<<<grid, 256>>>(X, S, Out, M, N, K);
}

// round 3
// speedup vs baseline: 2.5901x; 2.5901x over previous
#include <cuda_runtime.h>
#include <cuda_fp16.h>
#include <cstdint>

// ============================================================
// spikes = ((X @ ternarize(S)^T) >= 1), X[8192,4096] f32,
// S[4096,4096] f32, Out[8192,4096] f32.
// fp16 2-way split of X (hi+lo), W exact in fp16.
// GEMM M=8192 N=4096 K_eff=8192 via ldmatrix + mma.sync.m16n8k16
// (baseline PTX — harness compiles through compute_103, which
// rejects all sm_103a-gated tcgen05/TMEM instructions).
// BM=128 BN=256 BK=64, 3-stage cp.async pipeline, XOR swizzle.
// ============================================================

#define M_TOT 8192
#define N_TOT 4096
#define K_SRC 4096
#define K_EFF 8192
#define BM 128
#define BN 256
#define BK 64                       // halves per chunk = 128B rows
#define NCHUNKS (K_EFF / BK)        // 128
#define STAGES 3
#define A_STAGE_BYTES (BM * 128)    // 16KB
#define B_STAGE_BYTES (BN * 128)    // 32KB
#define STAGE_BYTES (A_STAGE_BYTES + B_STAGE_BYTES)   // 48KB
#define SMEM_TOTAL (STAGES * STAGE_BYTES)             // 147456

// fp16 scratch
__device__ __align__(128) __half g_A16[(size_t)M_TOT * K_EFF];  // 128 MB (hi | lo)
__device__ __align__(128) __half g_W16[(size_t)N_TOT * K_SRC];  // 32 MB

__device__ __forceinline__ uint32_t smem_u32(const void* p) {
    uint32_t a;
    asm("{ .reg .u64 t; cvta.to.shared.u64 t, %1; cvt.u32.u64 %0, t; }" : "=r"(a) : "l"(p));
    return a;
}

#define CP_ASYNC16(dst, src) \
    asm volatile("cp.async.cg.shared.global [%0], [%1], 16;" :: "r"(dst), "l"(src))
#define CP_COMMIT() asm volatile("cp.async.commit_group;")
#define CP_WAIT1()  asm volatile("cp.async.wait_group 1;")

#define LDSM4(r0, r1, r2, r3, addr) \
    asm volatile("ldmatrix.sync.aligned.m8n8.x4.shared.b16 {%0,%1,%2,%3}, [%4];" \
                 : "=r"(r0), "=r"(r1), "=r"(r2), "=r"(r3) : "r"(addr))

#define MMA16816(c, a, b0, b1) \
    asm volatile("mma.sync.aligned.m16n8k16.row.col.f32.f16.f16.f32 " \
                 "{%0,%1,%2,%3}, {%4,%5,%6,%7}, {%8,%9}, {%0,%1,%2,%3};" \
                 : "+f"((c)[0]), "+f"((c)[1]), "+f"((c)[2]), "+f"((c)[3]) \
                 : "r"((a)[0]), "r"((a)[1]), "r"((a)[2]), "r"((a)[3]), \
                   "r"(b0), "r"(b1))

// ---------------- convert kernels ----------------
__global__ __launch_bounds__(256)
void conv_a(const float* __restrict__ X) {
    size_t idx8 = (size_t)blockIdx.x * 256 + threadIdx.x;   // 0 .. 8192*4096/8-1
    size_t base = idx8 * 8;
    size_t row = base >> 12;           // /4096
    size_t col = base & 4095;
    float4 f0 = *reinterpret_cast<const float4*>(X + base);
    float4 f1 = *reinterpret_cast<const float4*>(X + base + 4);
    float xs[8] = {f0.x, f0.y, f0.z, f0.w, f1.x, f1.y, f1.z, f1.w};
    __half2 hh[4], ll[4];
#pragma unroll
    for (int e = 0; e < 4; e++) {
        __half a = __float2half_rn(xs[2 * e]);
        __half b = __float2half_rn(xs[2 * e + 1]);
        __half al = __float2half_rn(xs[2 * e] - __half2float(a));
        __half bl = __float2half_rn(xs[2 * e + 1] - __half2float(b));
        hh[e] = __halves2half2(a, b);
        ll[e] = __halves2half2(al, bl);
    }
    __half* dst = g_A16 + row * K_EFF + col;
    *reinterpret_cast<uint4*>(dst)          = *reinterpret_cast<uint4*>(hh);
    *reinterpret_cast<uint4*>(dst + K_SRC)  = *reinterpret_cast<uint4*>(ll);
}

__global__ __launch_bounds__(256)
void conv_w(const float* __restrict__ S) {
    size_t idx8 = (size_t)blockIdx.x * 256 + threadIdx.x;   // 0 .. 4096*4096/8-1
    size_t base = idx8 * 8;
    float4 f0 = *reinterpret_cast<const float4*>(S + base);
    float4 f1 = *reinterpret_cast<const float4*>(S + base + 4);
    float xs[8] = {f0.x, f0.y, f0.z, f0.w, f1.x, f1.y, f1.z, f1.w};
    __half2 ww[4];
#pragma unroll
    for (int e = 0; e < 4; e++) {
        float wa = (xs[2 * e]     > 1.0f) ? 1.0f : ((xs[2 * e]     < -1.0f) ? -1.0f : 0.0f);
        float wb = (xs[2 * e + 1] > 1.0f) ? 1.0f : ((xs[2 * e + 1] < -1.0f) ? -1.0f : 0.0f);
        ww[e] = __halves2half2(__float2half_rn(wa), __float2half_rn(wb));
    }
    *reinterpret_cast<uint4*>(g_W16 + base) = *reinterpret_cast<uint4*>(ww);
}

// ---------------- GEMM ----------------
__device__ __forceinline__ void stage_load(
    unsigned char* smem, int slot, int tid, int m0, int n0, int chunk) {
    uint32_t sA = smem_u32(smem) + slot * STAGE_BYTES;
    uint32_t sB = sA + A_STAGE_BYTES;

    // A: 128 rows x 128B; 2 threads/row, 4x16B each
    {
        int r = tid >> 1, h = tid & 1;
        const __half* ga = g_A16 + (size_t)(m0 + r) * K_EFF + chunk * BK + h * 32;
        uint32_t x = (uint32_t)(r & 7) * 16;
        uint32_t rb = (uint32_t)r * 128 ;
#pragma unroll
        for (int i = 0; i < 4; i++) {
            uint32_t off = (uint32_t)(h * 64 + i * 16) ^ x;
            CP_ASYNC16(sA + rb + off, ga + i * 8);
        }
    }
    // B: 256 rows x 128B; 1 thread/row, 8x16B each
    {
        int r = tid;
        const __half* gw = g_W16 + (size_t)(n0 + r) * K_SRC + (chunk & 63) * BK;
        uint32_t x = (uint32_t)(r & 7) * 16;
        uint32_t rb = (uint32_t)r * 128;
#pragma unroll
        for (int i = 0; i < 8; i++) {
            uint32_t off = (uint32_t)(i * 16) ^ x;
            CP_ASYNC16(sB + rb + off, gw + i * 8);
        }
    }
}

__global__ __launch_bounds__(256, 1)
void gemm16(float* __restrict__ Out) {
    extern __shared__ __align__(128) unsigned char smem[];
    const int tid = threadIdx.x;
    const int lane = tid & 31;
    const int wid = tid >> 5;
    const int wm = wid & 1;          // 2 m-warps (64 rows each)
    const int wn = wid >> 1;         // 4 n-warps (64 cols each)
    const int m0 = blockIdx.y * BM;
    const int n0 = blockIdx.x * BN;

    const uint32_t usmem = smem_u32(smem);

    // ldmatrix address precompute (offsets within stage)
    uint32_t rowoffA[4], rowoffB[4];
#pragma unroll
    for (int mt = 0; mt < 4; mt++)
        rowoffA[mt] = (uint32_t)(wm * 64 + mt * 16 + (lane & 15)) * 128;
#pragma unroll
    for (int nt = 0; nt < 4; nt++)
        rowoffB[nt] = (uint32_t)(wn * 64 + nt * 16 + ((lane >> 4) * 8 + (lane & 7))) * 128;
    const uint32_t xorv = (uint32_t)(lane & 7) * 16;
    const uint32_t colA_half = (uint32_t)(lane >> 4);        // +0/+1 16B unit
    const uint32_t colB_half = (uint32_t)((lane >> 3) & 1);  // +0/+1 16B unit

    float acc[4][8][4];
#pragma unroll
    for (int mt = 0; mt < 4; mt++)
#pragma unroll
        for (int nt = 0; nt < 8; nt++)
#pragma unroll
            for (int e = 0; e < 4; e++) acc[mt][nt][e] = 0.0f;

    // prologue
    stage_load(smem, 0, tid, m0, n0, 0); CP_COMMIT();
    stage_load(smem, 1, tid, m0, n0, 1); CP_COMMIT();
    CP_WAIT1();
    __syncthreads();

    for (int c = 0; c < NCHUNKS; c++) {
        const int s = c % STAGES;
        if (c + 2 < NCHUNKS)
            stage_load(smem, (c + 2) % STAGES, tid, m0, n0, c + 2);
        CP_COMMIT();

        const uint32_t uA = usmem + s * STAGE_BYTES;
        const uint32_t uB = uA + A_STAGE_BYTES;

#pragma unroll
        for (int ks = 0; ks < 4; ks++) {
            uint32_t a[4][4], b[4][4];
            const uint32_t cA = ((uint32_t)(ks * 2) + colA_half) * 16;
            const uint32_t cB = ((uint32_t)(ks * 2) + colB_half) * 16;
#pragma unroll
            for (int mt = 0; mt < 4; mt++)
                LDSM4(a[mt][0], a[mt][1], a[mt][2], a[mt][3],
                      uA + rowoffA[mt] + (cA ^ xorv));
#pragma unroll
            for (int nt = 0; nt < 4; nt++)
                LDSM4(b[nt][0], b[nt][1], b[nt][2], b[nt][3],
                      uB + rowoffB[nt] + (cB ^ xorv));
#pragma unroll
            for (int mt = 0; mt < 4; mt++)
#pragma unroll
                for (int nt = 0; nt < 4; nt++) {
                    MMA16816(acc[mt][2 * nt],     a[mt], b[nt][0], b[nt][1]);
                    MMA16816(acc[mt][2 * nt + 1], a[mt], b[nt][2], b[nt][3]);
                }
        }
        CP_WAIT1();
        __syncthreads();
    }

    // epilogue: threshold + store (float2 per half-row fragment)
#pragma unroll
    for (int mt = 0; mt < 4; mt++) {
        const int row = m0 + wm * 64 + mt * 16 + (lane >> 2);
#pragma unroll
        for (int nt = 0; nt < 8; nt++) {
            const int col = n0 + wn * 64 + nt * 8 + (lane & 3) * 2;
            float2 v0, v1;
            v0.x = (acc[mt][nt][0] >= 1.0f) ? 1.0f : 0.0f;
            v0.y = (acc[mt][nt][1] >= 1.0f) ? 1.0f : 0.0f;
            v1.x = (acc[mt][nt][2] >= 1.0f) ? 1.0f : 0.0f;
            v1.y = (acc[mt][nt][3] >= 1.0f) ? 1.0f : 0.0f;
            *reinterpret_cast<float2*>(Out + (size_t)row * N_TOT + col) = v0;
            *reinterpret_cast<float2*>(Out + (size_t)(row + 8) * N_TOT + col) = v1;
        }
    }
}

// ---------------- host ----------------
extern "C" void kernel_launch(void* const* d_in, const int* in_sizes, int n_in,
                              void* d_out, int out_size) {
    const float* X = (const float*)d_in[0];   // [8192, 4096]
    const float* S = (const float*)d_in[1];   // [4096, 4096]
    float* Out = (float*)d_out;

    cudaFuncSetAttribute(gemm16, cudaFuncAttributeMaxDynamicSharedMemorySize, SMEM_TOTAL);

    conv_a<<<(int)((size_t)M_TOT * K_SRC / 8 / 256), 256>>>(X);
    conv_w<<<(int)((size_t)N_TOT * K_SRC / 8 / 256), 256>>>(S);
    gemm16<<<dim3(N_TOT / BN, M_TOT / BM), 256, SMEM_TOTAL>>>(Out);
}

// round 4
// speedup vs baseline: 5.2444x; 2.0247x over previous
#include <cuda_runtime.h>
#include <cuda_fp16.h>
#include <cstdint>

// ============================================================
// spikes = ((X @ ternarize(S)^T) >= 1)
// X[8192,4096] f32, S[4096,4096] f32, Out[8192,4096] f32.
// fp16 2-way split of X (hi+lo exact), W exact fp16 (+-1/0).
// GEMM M=8192 N=4096 K_eff=8192, ldmatrix + mma.sync.m16n8k16.
// Stage fill via cp.async.bulk (1 instr / 16-32KB) from
// pre-tiled, pre-swizzled scratch -> removes LDGSTS issue bound
// that capped round 3 at 46% of mma.sync throughput.
// ============================================================

#define M_TOT 8192
#define N_TOT 4096
#define K_SRC 4096
#define K_EFF 8192
#define BM 128
#define BN 256
#define BK 64
#define NCHUNKS (K_EFF / BK)        // 128
#define STAGES 4
#define A_STAGE 16384               // 128 rows x 128B
#define B_STAGE 32768               // 256 rows x 128B
#define STAGE_BYTES (A_STAGE + B_STAGE)         // 48KB
#define SMEM_TOTAL (STAGES * STAGE_BYTES)       // 192KB

// pre-swizzled pre-tiled scratch
// A: [64 m128-tiles][128 chunks (0..63 hi, 64..127 lo)][16KB]
// B: [16 n256-tiles][64 chunks][32KB]
__device__ __align__(128) unsigned char g_A[64ull * 128 * A_STAGE];   // 128 MB
__device__ __align__(128) unsigned char g_B[16ull * 64 * B_STAGE];    // 32 MB

__device__ __forceinline__ uint32_t smem_u32(const void* p) {
    uint32_t a;
    asm("{ .reg .u64 t; cvta.to.shared.u64 t, %1; cvt.u32.u64 %0, t; }" : "=r"(a) : "l"(p));
    return a;
}
__device__ __forceinline__ uint32_t sw128(uint32_t off) {
    return off ^ ((off >> 3) & 0x70);
}

#define MBAR_INIT(addr, cnt) \
    asm volatile("mbarrier.init.shared.b64 [%0], %1;" :: "r"(addr), "r"(cnt) : "memory")
#define MBAR_ARRIVE(addr) \
    asm volatile("mbarrier.arrive.shared.b64 _, [%0];" :: "r"(addr) : "memory")
#define MBAR_EXPECT_TX(addr, bytes) \
    asm volatile("mbarrier.arrive.expect_tx.shared.b64 _, [%0], %1;" \
                 :: "r"(addr), "r"(bytes) : "memory")
#define MBAR_WAIT(addr, parity) do { \
    uint32_t _m = (addr); uint32_t _p = (parity); uint32_t _d; \
    asm volatile("{\n\t.reg .pred p;\n\t" \
        "mbarrier.try_wait.parity.acquire.cta.shared::cta.b64 p, [%1], %2;\n\t" \
        "selp.b32 %0, 1, 0, p;\n\t}" : "=r"(_d) : "r"(_m), "r"(_p) : "memory"); \
    if (!_d) { \
        asm volatile("{\n\t.reg .pred P1;\n\tWL_%=:\n\t" \
            "mbarrier.try_wait.parity.acquire.cta.shared::cta.b64 P1, [%0], %1, 0x989680;\n\t" \
            "@P1 bra.uni WD_%=;\n\tbra.uni WL_%=;\n\tWD_%=:\n\t}" \
            :: "r"(_m), "r"(_p) : "memory"); \
    } } while (0)
#define CP_BULK(dst, src, bytes, mbar) \
    asm volatile("cp.async.bulk.shared::cluster.global.mbarrier::complete_tx::bytes " \
                 "[%0], [%1], %2, [%3];" \
                 :: "r"(dst), "l"(src), "r"(bytes), "r"(mbar) : "memory")
#define FENCE_ASYNC_SHARED() asm volatile("fence.proxy.async.shared::cta;" ::: "memory")

#define LDSM4(r0, r1, r2, r3, addr) \
    asm volatile("ldmatrix.sync.aligned.m8n8.x4.shared.b16 {%0,%1,%2,%3}, [%4];" \
                 : "=r"(r0), "=r"(r1), "=r"(r2), "=r"(r3) : "r"(addr))
#define MMA16816(c, a, b0, b1) \
    asm volatile("mma.sync.aligned.m16n8k16.row.col.f32.f16.f16.f32 " \
                 "{%0,%1,%2,%3}, {%4,%5,%6,%7}, {%8,%9}, {%0,%1,%2,%3};" \
                 : "+f"((c)[0]), "+f"((c)[1]), "+f"((c)[2]), "+f"((c)[3]) \
                 : "r"((a)[0]), "r"((a)[1]), "r"((a)[2]), "r"((a)[3]), \
                   "r"(b0), "r"(b1))

// ---------------- convert kernels (pre-tile + pre-swizzle) ----------------
// A: hi = rn(x), lo = rn(x - hi). chunk c holds hi, chunk c+64 holds lo.
__global__ __launch_bounds__(256)
void conv_a(const float* __restrict__ X) {
    int t = blockIdx.x;           // m128 tile 0..63
    int c = blockIdx.y;           // k-chunk 0..63
    int tid = threadIdx.x;
    int r = tid >> 1, h = tid & 1;

    const float4* src = reinterpret_cast<const float4*>(
        X + (size_t)(t * 128 + r) * K_SRC + c * BK + h * 32);
    unsigned char* dhi = g_A + ((size_t)t * 128 + c) * A_STAGE;
    unsigned char* dlo = g_A + ((size_t)t * 128 + c + 64) * A_STAGE;

#pragma unroll
    for (int j = 0; j < 4; j++) {
        float4 f0 = src[j * 2], f1 = src[j * 2 + 1];
        float xs[8] = {f0.x, f0.y, f0.z, f0.w, f1.x, f1.y, f1.z, f1.w};
        __half2 hh[4], ll[4];
#pragma unroll
        for (int e = 0; e < 4; e++) {
            __half a = __float2half_rn(xs[2 * e]);
            __half b = __float2half_rn(xs[2 * e + 1]);
            __half al = __float2half_rn(xs[2 * e] - __half2float(a));
            __half bl = __float2half_rn(xs[2 * e + 1] - __half2float(b));
            hh[e] = __halves2half2(a, b);
            ll[e] = __halves2half2(al, bl);
        }
        uint32_t sw = sw128((uint32_t)r * 128 + h * 64 + j * 16);
        *reinterpret_cast<uint4*>(dhi + sw) = *reinterpret_cast<uint4*>(hh);
        *reinterpret_cast<uint4*>(dlo + sw) = *reinterpret_cast<uint4*>(ll);
    }
}

__global__ __launch_bounds__(256)
void conv_w(const float* __restrict__ S) {
    int nt = blockIdx.x;          // n256 tile 0..15
    int c = blockIdx.y;           // k-chunk 0..63
    int r = threadIdx.x;          // row 0..255

    const float4* src = reinterpret_cast<const float4*>(
        S + (size_t)(nt * 256 + r) * K_SRC + c * BK);
    unsigned char* dst = g_B + ((size_t)nt * 64 + c) * B_STAGE;

#pragma unroll
    for (int j = 0; j < 8; j++) {
        float4 f0 = src[j * 2], f1 = src[j * 2 + 1];
        float xs[8] = {f0.x, f0.y, f0.z, f0.w, f1.x, f1.y, f1.z, f1.w};
        __half2 ww[4];
#pragma unroll
        for (int e = 0; e < 4; e++) {
            float wa = (xs[2 * e]     > 1.0f) ? 1.0f : ((xs[2 * e]     < -1.0f) ? -1.0f : 0.0f);
            float wb = (xs[2 * e + 1] > 1.0f) ? 1.0f : ((xs[2 * e + 1] < -1.0f) ? -1.0f : 0.0f);
            ww[e] = __halves2half2(__float2half_rn(wa), __float2half_rn(wb));
        }
        uint32_t sw = sw128((uint32_t)r * 128 + j * 16);
        *reinterpret_cast<uint4*>(dst + sw) = *reinterpret_cast<uint4*>(ww);
    }
}

// ---------------- GEMM ----------------
__global__ __launch_bounds__(256, 1)
void gemm16(float* __restrict__ Out) {
    extern __shared__ __align__(128) unsigned char smem[];
    __shared__ __align__(8) uint64_t s_mbar[8];   // [0..3]=full, [4..7]=empty

    const int tid = threadIdx.x;
    const int lane = tid & 31;
    const int wid = tid >> 5;
    const int wm = wid & 1;
    const int wn = wid >> 1;
    const int m0 = blockIdx.y * BM;
    const int n0 = blockIdx.x * BN;

    const uint32_t usmem = smem_u32(smem);
    uint32_t mb_full[STAGES], mb_empty[STAGES];
#pragma unroll
    for (int s = 0; s < STAGES; s++) {
        mb_full[s]  = smem_u32(&s_mbar[s]);
        mb_empty[s] = smem_u32(&s_mbar[s + 4]);
    }

    const unsigned char* aSrc = g_A + (size_t)blockIdx.y * 128 * A_STAGE;
    const unsigned char* bSrc = g_B + (size_t)blockIdx.x * 64 * B_STAGE;

    if (tid == 0) {
#pragma unroll
        for (int s = 0; s < STAGES; s++) {
            MBAR_INIT(mb_full[s], 1);
            MBAR_INIT(mb_empty[s], 8);
        }
        FENCE_ASYNC_SHARED();
    }
    __syncthreads();

    // prologue: fill all 4 stages
    if (tid == 0) {
#pragma unroll
        for (int p = 0; p < STAGES; p++) {
            uint32_t dA = usmem + p * STAGE_BYTES;
            MBAR_EXPECT_TX(mb_full[p], (uint32_t)STAGE_BYTES);
            CP_BULK(dA,           aSrc + (size_t)p * A_STAGE,        A_STAGE, mb_full[p]);
            CP_BULK(dA + A_STAGE, bSrc + (size_t)(p & 63) * B_STAGE, B_STAGE, mb_full[p]);
        }
    }

    // fragment address precompute
    uint32_t rowoffA[4], rowoffB[4];
#pragma unroll
    for (int mt = 0; mt < 4; mt++)
        rowoffA[mt] = (uint32_t)(wm * 64 + mt * 16 + (lane & 15)) * 128;
#pragma unroll
    for (int nt = 0; nt < 4; nt++)
        rowoffB[nt] = (uint32_t)(wn * 64 + nt * 16 + ((lane >> 4) * 8 + (lane & 7))) * 128;
    const uint32_t xorv = (uint32_t)(lane & 7) * 16;
    const uint32_t colA_half = (uint32_t)(lane >> 4);
    const uint32_t colB_half = (uint32_t)((lane >> 3) & 1);

    float acc[4][8][4];
#pragma unroll
    for (int mt = 0; mt < 4; mt++)
#pragma unroll
        for (int nt = 0; nt < 8; nt++)
#pragma unroll
            for (int e = 0; e < 4; e++) acc[mt][nt][e] = 0.0f;

    for (int c = 0; c < NCHUNKS; c++) {
        const int st = c & 3;
        const int ph = (c >> 2) & 1;
        MBAR_WAIT(mb_full[st], ph);

        const uint32_t uA = usmem + st * STAGE_BYTES;
        const uint32_t uB = uA + A_STAGE;

#pragma unroll
        for (int ks = 0; ks < 4; ks++) {
            uint32_t a[4][4], b[4][4];
            const uint32_t cA = ((uint32_t)(ks * 2) + colA_half) * 16;
            const uint32_t cB = ((uint32_t)(ks * 2) + colB_half) * 16;
#pragma unroll
            for (int mt = 0; mt < 4; mt++)
                LDSM4(a[mt][0], a[mt][1], a[mt][2], a[mt][3],
                      uA + rowoffA[mt] + (cA ^ xorv));
#pragma unroll
            for (int nt = 0; nt < 4; nt++)
                LDSM4(b[nt][0], b[nt][1], b[nt][2], b[nt][3],
                      uB + rowoffB[nt] + (cB ^ xorv));
#pragma unroll
            for (int mt = 0; mt < 4; mt++)
#pragma unroll
                for (int nt = 0; nt < 4; nt++) {
                    MMA16816(acc[mt][2 * nt],     a[mt], b[nt][0], b[nt][1]);
                    MMA16816(acc[mt][2 * nt + 1], a[mt], b[nt][2], b[nt][3]);
                }
        }

        // all LDSM results consumed by mma issue -> safe to release stage
        if (lane == 0) MBAR_ARRIVE(mb_empty[st]);

        if (tid == 0 && c + STAGES < NCHUNKS) {
            MBAR_WAIT(mb_empty[st], ph);          // all 8 warps done with stage
            const int cn = c + STAGES;
            uint32_t dA = usmem + st * STAGE_BYTES;
            MBAR_EXPECT_TX(mb_full[st], (uint32_t)STAGE_BYTES);
            CP_BULK(dA,           aSrc + (size_t)cn * A_STAGE,        A_STAGE, mb_full[st]);
            CP_BULK(dA + A_STAGE, bSrc + (size_t)(cn & 63) * B_STAGE, B_STAGE, mb_full[st]);
        }
    }

    // epilogue
#pragma unroll
    for (int mt = 0; mt < 4; mt++) {
        const int row = m0 + wm * 64 + mt * 16 + (lane >> 2);
#pragma unroll
        for (int nt = 0; nt < 8; nt++) {
            const int col = n0 + wn * 64 + nt * 8 + (lane & 3) * 2;
            float2 v0, v1;
            v0.x = (acc[mt][nt][0] >= 1.0f) ? 1.0f : 0.0f;
            v0.y = (acc[mt][nt][1] >= 1.0f) ? 1.0f : 0.0f;
            v1.x = (acc[mt][nt][2] >= 1.0f) ? 1.0f : 0.0f;
            v1.y = (acc[mt][nt][3] >= 1.0f) ? 1.0f : 0.0f;
            *reinterpret_cast<float2*>(Out + (size_t)row * N_TOT + col) = v0;
            *reinterpret_cast<float2*>(Out + (size_t)(row + 8) * N_TOT + col) = v1;
        }
    }
}

// ---------------- host ----------------
extern "C" void kernel_launch(void* const* d_in, const int* in_sizes, int n_in,
                              void* d_out, int out_size) {
    const float* X = (const float*)d_in[0];   // [8192, 4096]
    const float* S = (const float*)d_in[1];   // [4096, 4096]
    float* Out = (float*)d_out;

    cudaFuncSetAttribute(gemm16, cudaFuncAttributeMaxDynamicSharedMemorySize, SMEM_TOTAL);

    conv_a<<<dim3(64, 64), 256>>>(X);
    conv_w<<<dim3(16, 64), 256>>>(S);
    gemm16<<<dim3(N_TOT / BN, M_TOT / BM), 256, SMEM_TOTAL>>>(Out);
}